// round 1
// baseline (speedup 1.0000x reference)
#include <cuda_runtime.h>
#include <cstdint>

#define N_NODES 50000
#define N_EDGES_MAX 800000
#define HID 128
#define LATENT 64
#define N_GRAPHS 256
#define BN_EPS 1e-5f

// ---------------- device scratch (static, no allocation) ----------------
__device__ float g_h0[N_NODES * HID];
__device__ float g_h1[N_NODES * HID];
__device__ float g_agg[N_NODES * HID];
__device__ float g_cnt[N_NODES];
__device__ float g_pooled[N_GRAPHS * HID];
__device__ float g_scale[HID];
__device__ float g_shift[HID];

// ---------------- small utility kernels ----------------
__global__ void zero_kernel(float* __restrict__ p, int n) {
    int i = blockIdx.x * blockDim.x + threadIdx.x;
    if (i < n) p[i] = 0.0f;
}

__global__ void count_kernel(const int* __restrict__ dst, int nE) {
    int i = blockIdx.x * blockDim.x + threadIdx.x;
    if (i < nE) atomicAdd(&g_cnt[dst[i]], 1.0f);
}

// ---------------- edge scatter: one warp per edge ----------------
// agg[dst] += h[src], 128 floats per edge, lane handles 4 floats.
__global__ __launch_bounds__(256) void scatter_kernel(
    const float* __restrict__ hin,
    const int* __restrict__ src, const int* __restrict__ dst, int nE)
{
    int w = (blockIdx.x * blockDim.x + threadIdx.x) >> 5;
    int lane = threadIdx.x & 31;
    if (w >= nE) return;
    int s = __ldg(&src[w]);
    int d = __ldg(&dst[w]);
    float4 v = *reinterpret_cast<const float4*>(hin + (size_t)s * HID + lane * 4);
    float* ag = g_agg + (size_t)d * HID + lane * 4;
    atomicAdd(ag + 0, v.x);
    atomicAdd(ag + 1, v.y);
    atomicAdd(ag + 2, v.z);
    atomicAdd(ag + 3, v.w);
}

// ---------------- fused SAGE GEMM ----------------
// hout[m, n] = relu( sum_k mean[m,k]*Wl[k,n] + bl[n] + sum_k hin[m,k]*Wr[k,n] )
// A = [mean | hin]  (M x 256),  B = [Wl ; Wr]  (256 x 128)
// Tile: 128x128 per block, BK=32, 256 threads, 8x8 register tile per thread,
// inner product done with packed fma.rn.f32x2 (double-rate fp32 on sm_103a).
__device__ __forceinline__ unsigned long long pack2(float v) {
    unsigned long long r;
    unsigned int u = __float_as_uint(v);
    asm("mov.b64 %0, {%1, %1};" : "=l"(r) : "r"(u));
    return r;
}
__device__ __forceinline__ void ffma2(unsigned long long& acc,
                                      unsigned long long a2,
                                      unsigned long long b2) {
    asm("fma.rn.f32x2 %0, %1, %2, %0;" : "+l"(acc) : "l"(a2), "l"(b2));
}

__global__ __launch_bounds__(256) void sage_gemm_kernel(
    const float* __restrict__ hin,
    const float* __restrict__ Wl,   // [128,128] row-major (k,n)
    const float* __restrict__ Wr,   // [128,128]
    const float* __restrict__ bl,   // [128]
    float* __restrict__ hout)
{
    __shared__ float As[128][33];   // [m][k-chunk], pad 33 -> conflict-free
    __shared__ float Bs[32][128];   // [k][n]

    const int tid = threadIdx.x;
    const int m0 = (tid >> 4) << 3;     // 0..120
    const int n0 = (tid & 15) << 3;     // 0..120
    const int rowBase = blockIdx.x * 128;

    unsigned long long acc[8][4];
    const unsigned long long z = pack2(0.0f);
#pragma unroll
    for (int i = 0; i < 8; i++)
#pragma unroll
        for (int p = 0; p < 4; p++) acc[i][p] = z;

    for (int kb = 0; kb < 256; kb += 32) {
        // --- load B chunk (coalesced float4, no transpose) ---
        const float* Bsrc = (kb < 128) ? (Wl + kb * 128) : (Wr + (kb - 128) * 128);
#pragma unroll
        for (int i = 0; i < 4; i++) {
            int idx = tid + i * 256;            // float4 index 0..1023
            int kk = idx >> 5;                  // 0..31
            int nn = (idx & 31) << 2;           // 0..124
            float4 v = *reinterpret_cast<const float4*>(Bsrc + kk * 128 + nn);
            *reinterpret_cast<float4*>(&Bs[kk][nn]) = v;
        }
        // --- load A chunk: mean (agg/cnt) for kb<128, hin for kb>=128 ---
        const bool neigh = (kb < 128);
#pragma unroll
        for (int i = 0; i < 4; i++) {
            int idx = tid + i * 256;            // 0..1023
            int m = idx >> 3;                   // 0..127
            int kq = (idx & 7) << 2;            // 0,4,...,28
            int gm = rowBase + m;
            float4 v = make_float4(0.f, 0.f, 0.f, 0.f);
            if (gm < N_NODES) {
                if (neigh) {
                    v = *reinterpret_cast<const float4*>(g_agg + (size_t)gm * HID + kb + kq);
                    float inv = 1.0f / fmaxf(g_cnt[gm], 1.0f);
                    v.x *= inv; v.y *= inv; v.z *= inv; v.w *= inv;
                } else {
                    v = *reinterpret_cast<const float4*>(hin + (size_t)gm * HID + (kb - 128) + kq);
                }
            }
            As[m][kq + 0] = v.x;
            As[m][kq + 1] = v.y;
            As[m][kq + 2] = v.z;
            As[m][kq + 3] = v.w;
        }
        __syncthreads();

#pragma unroll 4
        for (int k = 0; k < 32; k++) {
            unsigned long long b2[4];
            {
                ulonglong2 t0 = *reinterpret_cast<const ulonglong2*>(&Bs[k][n0]);
                ulonglong2 t1 = *reinterpret_cast<const ulonglong2*>(&Bs[k][n0 + 4]);
                b2[0] = t0.x; b2[1] = t0.y; b2[2] = t1.x; b2[3] = t1.y;
            }
#pragma unroll
            for (int i = 0; i < 8; i++) {
                unsigned long long a2 = pack2(As[m0 + i][k]);
                ffma2(acc[i][0], a2, b2[0]);
                ffma2(acc[i][1], a2, b2[1]);
                ffma2(acc[i][2], a2, b2[2]);
                ffma2(acc[i][3], a2, b2[3]);
            }
        }
        __syncthreads();
    }

    // --- epilogue: + bias, relu, store ---
#pragma unroll
    for (int i = 0; i < 8; i++) {
        int gm = rowBase + m0 + i;
        if (gm >= N_NODES) break;
#pragma unroll
        for (int p = 0; p < 4; p++) {
            float lo = __uint_as_float((unsigned int)(acc[i][p] & 0xFFFFFFFFull));
            float hi = __uint_as_float((unsigned int)(acc[i][p] >> 32));
            int n = n0 + 2 * p;
            float2 o;
            o.x = fmaxf(lo + bl[n], 0.0f);
            o.y = fmaxf(hi + bl[n + 1], 0.0f);
            *reinterpret_cast<float2*>(hout + (size_t)gm * HID + n) = o;
        }
    }
}

// ---------------- pooled = segment_sum(h, batch) (batch is sorted) ----------------
// block = 128 threads (thread = channel), block handles 128 consecutive rows,
// register-accumulate per segment, flush one atomic at each boundary.
__global__ __launch_bounds__(128) void pool_kernel(
    const float* __restrict__ hin, const int* __restrict__ batch)
{
    int base = blockIdx.x * 128;
    int c = threadIdx.x;
    int limit = N_NODES - base;
    if (limit > 128) limit = 128;
    if (limit <= 0) return;
    int cur = __ldg(&batch[base]);
    float acc = 0.0f;
    for (int r = 0; r < limit; r++) {
        int b = __ldg(&batch[base + r]);
        if (b != cur) {
            atomicAdd(&g_pooled[cur * HID + c], acc);
            acc = 0.0f;
            cur = b;
        }
        acc += hin[(size_t)(base + r) * HID + c];
    }
    atomicAdd(&g_pooled[cur * HID + c], acc);
}

// ---------------- batchnorm statistics over the 256 graphs ----------------
__global__ __launch_bounds__(128) void bn_kernel(
    const float* __restrict__ gamma, const float* __restrict__ beta)
{
    int c = threadIdx.x;
    float s = 0.0f, s2 = 0.0f;
    for (int g = 0; g < N_GRAPHS; g++) {
        float v = g_pooled[g * HID + c];
        s += v;
        s2 += v * v;
    }
    float mu = s * (1.0f / N_GRAPHS);
    float var = s2 * (1.0f / N_GRAPHS) - mu * mu;
    float sc = gamma[c] * rsqrtf(var + BN_EPS);
    g_scale[c] = sc;
    g_shift[c] = beta[c] - mu * sc;
}

// ---------------- final FC: out[g,l] = normed[g,:] @ fcW + fcb ----------------
__global__ __launch_bounds__(64) void final_kernel(
    const float* __restrict__ fcW, const float* __restrict__ fcb,
    float* __restrict__ out)
{
    __shared__ float row[HID];
    int g = blockIdx.x;
    int l = threadIdx.x;
    for (int c = l; c < HID; c += 64)
        row[c] = g_pooled[g * HID + c] * g_scale[c] + g_shift[c];
    __syncthreads();
    float acc = fcb[l];
#pragma unroll
    for (int c = 0; c < HID; c++)
        acc += row[c] * __ldg(&fcW[c * LATENT + l]);
    out[g * LATENT + l] = acc;
}

// ---------------- launch ----------------
extern "C" void kernel_launch(void* const* d_in, const int* in_sizes, int n_in,
                              void* d_out, int out_size)
{
    const float* x     = (const float*)d_in[0];
    const int*   ei    = (const int*)d_in[1];
    const int*   batch = (const int*)d_in[2];
    const float* Wl    = (const float*)d_in[3];
    const float* bl    = (const float*)d_in[4];
    const float* Wr    = (const float*)d_in[5];
    const float* gamma = (const float*)d_in[6];
    const float* beta  = (const float*)d_in[7];
    const float* fcW   = (const float*)d_in[8];
    const float* fcb   = (const float*)d_in[9];
    float* out = (float*)d_out;

    const int E = in_sizes[1] / 2;
    const int* src = ei;
    const int* dst = ei + E;

    float *h0, *h1, *agg, *cnt, *pooled;
    cudaGetSymbolAddress((void**)&h0, g_h0);
    cudaGetSymbolAddress((void**)&h1, g_h1);
    cudaGetSymbolAddress((void**)&agg, g_agg);
    cudaGetSymbolAddress((void**)&cnt, g_cnt);
    cudaGetSymbolAddress((void**)&pooled, g_pooled);

    // degree counts + pooled zero (once per call)
    zero_kernel<<<(N_NODES + 255) / 256, 256>>>(cnt, N_NODES);
    zero_kernel<<<(N_GRAPHS * HID + 255) / 256, 256>>>(pooled, N_GRAPHS * HID);
    count_kernel<<<(E + 255) / 256, 256>>>(dst, E);

    const int gemm_blocks = (N_NODES + 127) / 128;
    const int scat_blocks = (E + 7) / 8;  // 8 warps per 256-thread block
    const int nagg = N_NODES * HID;

    const float* hin = x;
    float* houts[3] = { h0, h1, h0 };
    for (int layer = 0; layer < 3; layer++) {
        zero_kernel<<<(nagg + 255) / 256, 256>>>(agg, nagg);
        scatter_kernel<<<scat_blocks, 256>>>(hin, src, dst, E);
        sage_gemm_kernel<<<gemm_blocks, 256>>>(
            hin, Wl + layer * HID * HID, Wr + layer * HID * HID,
            bl + layer * HID, houts[layer]);
        hin = houts[layer];
    }

    pool_kernel<<<(N_NODES + 127) / 128, 128>>>(h0, batch);
    bn_kernel<<<1, 128>>>(gamma, beta);
    final_kernel<<<N_GRAPHS, 64>>>(fcW, fcb, out);
}

// round 2
// speedup vs baseline: 1.7541x; 1.7541x over previous
#include <cuda_runtime.h>
#include <cstdint>

#define N_NODES 50000
#define HID 128
#define LATENT 64
#define N_GRAPHS 256
#define BN_EPS 1e-5f
#define SCAN_T 1024
#define SCAN_CHUNK 49   // 1024*49 = 50176 >= 50000

// ---------------- device scratch (static, no allocation) ----------------
__device__ float g_h0[N_NODES * HID];
__device__ float g_h1[N_NODES * HID];
__device__ float g_agg[N_NODES * HID];        // holds per-node MEAN of neighbors
__device__ int   g_deg[N_NODES];
__device__ int   g_rowstart[N_NODES + 1];
__device__ int   g_cursor[N_NODES];
__device__ int   g_csr[800000 * 2];           // headroom for E
__device__ float g_pooled[N_GRAPHS * HID];
__device__ float g_scale[HID];
__device__ float g_shift[HID];

// ---------------- small utility kernels ----------------
__global__ void zero_f(float* __restrict__ p, int n) {
    int i = blockIdx.x * blockDim.x + threadIdx.x;
    if (i < n) p[i] = 0.0f;
}
__global__ void zero_i(int* __restrict__ p, int n) {
    int i = blockIdx.x * blockDim.x + threadIdx.x;
    if (i < n) p[i] = 0;
}
__global__ void count_kernel(const int* __restrict__ dst, int nE) {
    int i = blockIdx.x * blockDim.x + threadIdx.x;
    if (i < nE) atomicAdd(&g_deg[dst[i]], 1);
}

// single-block scan over 50K degree counts -> rowstart + cursor
__global__ __launch_bounds__(SCAN_T) void scan_kernel() {
    __shared__ int sums[SCAN_T];
    int t = threadIdx.x;
    int base = t * SCAN_CHUNK;
    int s = 0;
#pragma unroll 7
    for (int i = 0; i < SCAN_CHUNK; i++) {
        int idx = base + i;
        if (idx < N_NODES) s += g_deg[idx];
    }
    sums[t] = s;
    __syncthreads();
    for (int off = 1; off < SCAN_T; off <<= 1) {
        int v = 0;
        if (t >= off) v = sums[t - off];
        __syncthreads();
        if (t >= off) sums[t] += v;
        __syncthreads();
    }
    int run = (t == 0) ? 0 : sums[t - 1];
    for (int i = 0; i < SCAN_CHUNK; i++) {
        int idx = base + i;
        if (idx < N_NODES) {
            g_rowstart[idx] = run;
            g_cursor[idx] = run;
            run += g_deg[idx];
        }
    }
    if (t == SCAN_T - 1) g_rowstart[N_NODES] = run;
}

__global__ void fill_kernel(const int* __restrict__ src,
                            const int* __restrict__ dst, int nE) {
    int i = blockIdx.x * blockDim.x + threadIdx.x;
    if (i < nE) {
        int d = dst[i];
        int pos = atomicAdd(&g_cursor[d], 1);
        g_csr[pos] = src[i];
    }
}

// ---------------- gather: mean over incoming neighbors ----------------
// block = one node (128 threads = channels), unroll-4 over neighbor rows.
__global__ __launch_bounds__(128) void gather_kernel(const float* __restrict__ hin) {
    int node = blockIdx.x;
    int c = threadIdx.x;
    int s0 = g_rowstart[node];
    int s1 = g_rowstart[node + 1];
    float acc = 0.0f;
    int j = s0;
    for (; j + 4 <= s1; j += 4) {
        int i0 = __ldg(&g_csr[j + 0]);
        int i1 = __ldg(&g_csr[j + 1]);
        int i2 = __ldg(&g_csr[j + 2]);
        int i3 = __ldg(&g_csr[j + 3]);
        float a = hin[(size_t)i0 * HID + c];
        float b = hin[(size_t)i1 * HID + c];
        float d = hin[(size_t)i2 * HID + c];
        float e = hin[(size_t)i3 * HID + c];
        acc += (a + b) + (d + e);
    }
    for (; j < s1; j++)
        acc += hin[(size_t)__ldg(&g_csr[j]) * HID + c];
    int deg = s1 - s0;
    float inv = 1.0f / (float)(deg > 0 ? deg : 1);
    g_agg[(size_t)node * HID + c] = acc * inv;
}

// ---------------- fused SAGE GEMM ----------------
// hout[m,n] = relu( mean[m,:]@Wl + bl + hin[m,:]@Wr ),  packed f32x2 FMA.
__device__ __forceinline__ unsigned long long pack2(float v) {
    unsigned long long r;
    unsigned int u = __float_as_uint(v);
    asm("mov.b64 %0, {%1, %1};" : "=l"(r) : "r"(u));
    return r;
}
__device__ __forceinline__ void ffma2(unsigned long long& acc,
                                      unsigned long long a2,
                                      unsigned long long b2) {
    asm("fma.rn.f32x2 %0, %1, %2, %0;" : "+l"(acc) : "l"(a2), "l"(b2));
}

__global__ __launch_bounds__(256) void sage_gemm_kernel(
    const float* __restrict__ hin,
    const float* __restrict__ Wl,   // [128,128] (k,n)
    const float* __restrict__ Wr,   // [128,128]
    const float* __restrict__ bl,   // [128]
    float* __restrict__ hout)
{
    __shared__ float As[128][33];
    __shared__ float Bs[32][128];

    const int tid = threadIdx.x;
    const int m0 = (tid >> 4) << 3;
    const int n0 = (tid & 15) << 3;
    const int rowBase = blockIdx.x * 128;

    unsigned long long acc[8][4];
    const unsigned long long z = pack2(0.0f);
#pragma unroll
    for (int i = 0; i < 8; i++)
#pragma unroll
        for (int p = 0; p < 4; p++) acc[i][p] = z;

    for (int kb = 0; kb < 256; kb += 32) {
        const float* Bsrc = (kb < 128) ? (Wl + kb * 128) : (Wr + (kb - 128) * 128);
#pragma unroll
        for (int i = 0; i < 4; i++) {
            int idx = tid + i * 256;
            int kk = idx >> 5;
            int nn = (idx & 31) << 2;
            float4 v = *reinterpret_cast<const float4*>(Bsrc + kk * 128 + nn);
            *reinterpret_cast<float4*>(&Bs[kk][nn]) = v;
        }
        const float* Asrc = (kb < 128) ? (g_agg + kb) : (hin + (kb - 128));
#pragma unroll
        for (int i = 0; i < 4; i++) {
            int idx = tid + i * 256;
            int m = idx >> 3;
            int kq = (idx & 7) << 2;
            int gm = rowBase + m;
            float4 v = make_float4(0.f, 0.f, 0.f, 0.f);
            if (gm < N_NODES)
                v = *reinterpret_cast<const float4*>(Asrc + (size_t)gm * HID + kq);
            As[m][kq + 0] = v.x;
            As[m][kq + 1] = v.y;
            As[m][kq + 2] = v.z;
            As[m][kq + 3] = v.w;
        }
        __syncthreads();

#pragma unroll 4
        for (int k = 0; k < 32; k++) {
            unsigned long long b2[4];
            {
                ulonglong2 t0 = *reinterpret_cast<const ulonglong2*>(&Bs[k][n0]);
                ulonglong2 t1 = *reinterpret_cast<const ulonglong2*>(&Bs[k][n0 + 4]);
                b2[0] = t0.x; b2[1] = t0.y; b2[2] = t1.x; b2[3] = t1.y;
            }
#pragma unroll
            for (int i = 0; i < 8; i++) {
                unsigned long long a2 = pack2(As[m0 + i][k]);
                ffma2(acc[i][0], a2, b2[0]);
                ffma2(acc[i][1], a2, b2[1]);
                ffma2(acc[i][2], a2, b2[2]);
                ffma2(acc[i][3], a2, b2[3]);
            }
        }
        __syncthreads();
    }

#pragma unroll
    for (int i = 0; i < 8; i++) {
        int gm = rowBase + m0 + i;
        if (gm >= N_NODES) break;
#pragma unroll
        for (int p = 0; p < 4; p++) {
            float lo = __uint_as_float((unsigned int)(acc[i][p] & 0xFFFFFFFFull));
            float hi = __uint_as_float((unsigned int)(acc[i][p] >> 32));
            int n = n0 + 2 * p;
            float2 o;
            o.x = fmaxf(lo + bl[n], 0.0f);
            o.y = fmaxf(hi + bl[n + 1], 0.0f);
            *reinterpret_cast<float2*>(hout + (size_t)gm * HID + n) = o;
        }
    }
}

// ---------------- pooled = segment_sum(h, batch) (batch is sorted) ----------------
__global__ __launch_bounds__(128) void pool_kernel(
    const float* __restrict__ hin, const int* __restrict__ batch)
{
    int base = blockIdx.x * 128;
    int c = threadIdx.x;
    int limit = N_NODES - base;
    if (limit > 128) limit = 128;
    if (limit <= 0) return;
    int cur = __ldg(&batch[base]);
    float acc = 0.0f;
    for (int r = 0; r < limit; r++) {
        int b = __ldg(&batch[base + r]);
        if (b != cur) {
            atomicAdd(&g_pooled[cur * HID + c], acc);
            acc = 0.0f;
            cur = b;
        }
        acc += hin[(size_t)(base + r) * HID + c];
    }
    atomicAdd(&g_pooled[cur * HID + c], acc);
}

// ---------------- batchnorm statistics over the 256 graphs ----------------
__global__ __launch_bounds__(128) void bn_kernel(
    const float* __restrict__ gamma, const float* __restrict__ beta)
{
    int c = threadIdx.x;
    float s = 0.0f, s2 = 0.0f;
    for (int g = 0; g < N_GRAPHS; g++) {
        float v = g_pooled[g * HID + c];
        s += v;
        s2 += v * v;
    }
    float mu = s * (1.0f / N_GRAPHS);
    float var = s2 * (1.0f / N_GRAPHS) - mu * mu;
    float sc = gamma[c] * rsqrtf(var + BN_EPS);
    g_scale[c] = sc;
    g_shift[c] = beta[c] - mu * sc;
}

// ---------------- final FC ----------------
__global__ __launch_bounds__(64) void final_kernel(
    const float* __restrict__ fcW, const float* __restrict__ fcb,
    float* __restrict__ out)
{
    __shared__ float row[HID];
    int g = blockIdx.x;
    int l = threadIdx.x;
    for (int c = l; c < HID; c += 64)
        row[c] = g_pooled[g * HID + c] * g_scale[c] + g_shift[c];
    __syncthreads();
    float acc = fcb[l];
#pragma unroll
    for (int c = 0; c < HID; c++)
        acc += row[c] * __ldg(&fcW[c * LATENT + l]);
    out[g * LATENT + l] = acc;
}

// ---------------- launch ----------------
extern "C" void kernel_launch(void* const* d_in, const int* in_sizes, int n_in,
                              void* d_out, int out_size)
{
    const float* x     = (const float*)d_in[0];
    const int*   ei    = (const int*)d_in[1];
    const int*   batch = (const int*)d_in[2];
    const float* Wl    = (const float*)d_in[3];
    const float* bl    = (const float*)d_in[4];
    const float* Wr    = (const float*)d_in[5];
    const float* gamma = (const float*)d_in[6];
    const float* beta  = (const float*)d_in[7];
    const float* fcW   = (const float*)d_in[8];
    const float* fcb   = (const float*)d_in[9];
    float* out = (float*)d_out;

    const int E = in_sizes[1] / 2;
    const int* src = ei;
    const int* dst = ei + E;

    float *h0, *h1, *pooled;
    int *deg;
    cudaGetSymbolAddress((void**)&h0, g_h0);
    cudaGetSymbolAddress((void**)&h1, g_h1);
    cudaGetSymbolAddress((void**)&pooled, g_pooled);
    cudaGetSymbolAddress((void**)&deg, g_deg);

    // ---- CSR build (once per call, reused by all 3 layers) ----
    zero_i<<<(N_NODES + 255) / 256, 256>>>(deg, N_NODES);
    zero_f<<<(N_GRAPHS * HID + 255) / 256, 256>>>(pooled, N_GRAPHS * HID);
    count_kernel<<<(E + 255) / 256, 256>>>(dst, E);
    scan_kernel<<<1, SCAN_T>>>();
    fill_kernel<<<(E + 255) / 256, 256>>>(src, dst, E);

    const int gemm_blocks = (N_NODES + 127) / 128;

    const float* hin = x;
    float* houts[3] = { h0, h1, h0 };
    for (int layer = 0; layer < 3; layer++) {
        gather_kernel<<<N_NODES, 128>>>(hin);
        sage_gemm_kernel<<<gemm_blocks, 256>>>(
            hin, Wl + layer * HID * HID, Wr + layer * HID * HID,
            bl + layer * HID, houts[layer]);
        hin = houts[layer];
    }

    pool_kernel<<<(N_NODES + 127) / 128, 128>>>(h0, batch);
    bn_kernel<<<1, 128>>>(gamma, beta);
    final_kernel<<<N_GRAPHS, 64>>>(fcW, fcb, out);
}